// round 1
// baseline (speedup 1.0000x reference)
#include <cuda_runtime.h>
#include <cuda_bf16.h>

typedef unsigned long long u64;

#define NMAX 100000

// ---------------- device scratch (no allocations allowed) ----------------
__device__ float g_agg[NMAX];
__device__ int   g_deg[NMAX];
__device__ float g_tmp[NMAX];
__device__ int   g_degmax;
__device__ float g_sum_agg;
__device__ float g_sum_score;
__device__ float g_sumsq;

// ---------------- smem weight layout (units: u64 {w,w} pairs) ------------
// All matrix row bases kept at even u64 index so LDS.128 (ulonglong2) is
// 16B-aligned. Hidden rows padded 35 -> 36.
#define OFF_SW 0        // 35 x 10, stride 10           (350)
#define OFF_SB 350      // 35                           (35)
#define OFF_HW 386      // 3 x 35 x 35, stride 36       (3780)
#define OFF_HB 4166     // 105                          (105)
#define OFF_EW 4272     // 5 x 35, stride 36            (180)
#define OFF_EB 4452     // 5                            (5)
#define NET_STRIDE 4458
#define SMEM_PAIRS (2 * NET_STRIDE)
#define SMEM_BYTES (SMEM_PAIRS * 8)

// ---------------- packed f32x2 helpers ----------------
__device__ __forceinline__ u64 fma2(u64 a, u64 b, u64 c) {
    u64 d;
    asm("fma.rn.f32x2 %0, %1, %2, %3;" : "=l"(d) : "l"(a), "l"(b), "l"(c));
    return d;
}
__device__ __forceinline__ u64 pk(float lo, float hi) {
    return ((u64)__float_as_uint(hi) << 32) | (u64)__float_as_uint(lo);
}
__device__ __forceinline__ float lo32(u64 a) { return __uint_as_float((unsigned)a); }
__device__ __forceinline__ float hi32(u64 a) { return __uint_as_float((unsigned)(a >> 32)); }
__device__ __forceinline__ u64 relu2(u64 a) {
    float l = fmaxf(lo32(a), 0.0f);
    float h = fmaxf(hi32(a), 0.0f);
    return pk(l, h);
}
__device__ __forceinline__ float sigmoidf(float v) {
    return 1.0f / (1.0f + __expf(-v));
}

// Dense layer on packed pairs. w rows at stride STRIDE (pairs), 16B-aligned.
template<int NOUT, int NIN, int STRIDE, bool RELU>
__device__ __forceinline__ void dense(const u64* __restrict__ w,
                                      const u64* __restrict__ b,
                                      const u64 (&x)[NIN], u64 (&y)[NOUT]) {
#pragma unroll
    for (int j = 0; j < NOUT; j++) {
        u64 acc = b[j];
        const u64* wr = w + j * STRIDE;
#pragma unroll
        for (int i = 0; i + 1 < NIN; i += 2) {
            ulonglong2 w2 = *reinterpret_cast<const ulonglong2*>(wr + i);
            acc = fma2(w2.x, x[i], acc);
            acc = fma2(w2.y, x[i + 1], acc);
        }
        if (NIN & 1) acc = fma2(wr[NIN - 1], x[NIN - 1], acc);
        y[j] = RELU ? relu2(acc) : acc;
    }
}

// ---------------- kernels ----------------
__global__ void zero_kernel(int N) {
    int i = blockIdx.x * blockDim.x + threadIdx.x;
    if (i < N) { g_agg[i] = 0.0f; g_deg[i] = 0; }
    if (i == 0) { g_degmax = 0; g_sum_agg = 0.0f; g_sum_score = 0.0f; g_sumsq = 0.0f; }
}

__global__ void __launch_bounds__(128) edge_kernel(
    const float* __restrict__ score,
    const int*   __restrict__ edge_idx,
    const float* __restrict__ outcome,
    const float* __restrict__ Rsw, const float* __restrict__ Rsb,
    const float* __restrict__ Rhw, const float* __restrict__ Rhb,
    const float* __restrict__ Rew, const float* __restrict__ Reb,
    const float* __restrict__ Psw, const float* __restrict__ Psb,
    const float* __restrict__ Phw, const float* __restrict__ Phb,
    const float* __restrict__ Pew, const float* __restrict__ Peb,
    int E)
{
    extern __shared__ u64 wsm[];
    const int t = threadIdx.x, nt = blockDim.x;

    // ---- cooperative duplicated-pair weight load ----
    auto dupm = [&](const float* __restrict__ s, u64* d, int rows, int cols, int stride) {
        int n = rows * cols;
        for (int k = t; k < n; k += nt) {
            int r = k / cols, c = k - r * cols;
            unsigned wb = __float_as_uint(s[k]);
            d[r * stride + c] = ((u64)wb << 32) | (u64)wb;
        }
    };
    auto dupv = [&](const float* __restrict__ s, u64* d, int n) {
        for (int k = t; k < n; k += nt) {
            unsigned wb = __float_as_uint(s[k]);
            d[k] = ((u64)wb << 32) | (u64)wb;
        }
    };
    dupm(Rsw, wsm + OFF_SW, 35, 10, 10);
    dupv(Rsb, wsm + OFF_SB, 35);
    dupm(Rhw, wsm + OFF_HW, 105, 35, 36);
    dupv(Rhb, wsm + OFF_HB, 105);
    dupm(Rew, wsm + OFF_EW, 5, 35, 36);   // only first 5 output rows needed
    dupv(Reb, wsm + OFF_EB, 5);
    u64* wp = wsm + NET_STRIDE;
    dupm(Psw, wp + OFF_SW, 35, 10, 10);
    dupv(Psb, wp + OFF_SB, 35);
    dupm(Phw, wp + OFF_HW, 105, 35, 36);
    dupv(Phb, wp + OFF_HB, 105);
    dupm(Pew, wp + OFF_EW, 5, 35, 36);
    dupv(Peb, wp + OFF_EB, 5);
    __syncthreads();

    const int P = (E + 1) >> 1;
    const int p = blockIdx.x * blockDim.x + t;
    if (p >= P) return;

    const int  e0 = 2 * p;
    const bool v1 = (e0 + 1) < E;
    const int* ei0 = edge_idx + (size_t)e0 * 10;

    int idx[20];
    if (v1) {
#pragma unroll
        for (int k = 0; k < 5; k++) {   // 20 ints, 16B-aligned (80B per pair)
            int4 q4 = reinterpret_cast<const int4*>(ei0)[k];
            idx[4 * k + 0] = q4.x; idx[4 * k + 1] = q4.y;
            idx[4 * k + 2] = q4.z; idx[4 * k + 3] = q4.w;
        }
    } else {
#pragma unroll
        for (int k = 0; k < 10; k++) { idx[k] = ei0[k]; idx[10 + k] = ei0[k]; }
    }

    float xa[10], xb[10];
#pragma unroll
    for (int i = 0; i < 10; i++) { xa[i] = score[idx[i]]; xb[i] = score[idx[10 + i]]; }

    const float oc0 = outcome[e0];
    const float oc1 = v1 ? outcome[e0 + 1] : oc0;
    const bool  o0 = oc0 > 0.0f, o1 = oc1 > 0.0f;

    // R-net input orientation: forward if outcome>0 else reversed (lane-wise).
    u64 xr[10];
#pragma unroll
    for (int i = 0; i < 10; i++)
        xr[i] = pk(o0 ? xa[i] : xa[9 - i], o1 ? xb[i] : xb[9 - i]);

    u64 rr[5], qq[5];
#pragma unroll 1
    for (int net = 0; net < 2; net++) {   // net 0 = R, net 1 = P (input reversed)
        const u64* Wb = wsm + net * NET_STRIDE;
        u64 xin[10];
#pragma unroll
        for (int i = 0; i < 10; i++) xin[i] = net ? xr[9 - i] : xr[i];

        u64 h[35], g[35], o5[5];
        dense<35, 10, 10, true >(Wb + OFF_SW,        Wb + OFF_SB,      xin, h);
        dense<35, 35, 36, true >(Wb + OFF_HW,        Wb + OFF_HB,      h,   g);
        dense<35, 35, 36, true >(Wb + OFF_HW + 1260, Wb + OFF_HB + 35, g,   h);
        dense<35, 35, 36, true >(Wb + OFF_HW + 2520, Wb + OFF_HB + 70, h,   g);
        dense< 5, 35, 36, false>(Wb + OFF_EW,        Wb + OFF_EB,      g,   o5);
#pragma unroll
        for (int j = 0; j < 5; j++) { if (net == 0) rr[j] = o5[j]; else qq[j] = o5[j]; }
    }

    // ---- scatter: R always +sigmoid, P always -sigmoid.
    // R slot base = outcome>0 ? 0 : 5 ; P slot base = the other half.
    {
        const int bR = o0 ? 0 : 5, bP = 5 - bR;
#pragma unroll
        for (int j = 0; j < 5; j++) {
            atomicAdd(&g_agg[idx[bR + j]],  sigmoidf(lo32(rr[j])));
            atomicAdd(&g_agg[idx[bP + j]], -sigmoidf(lo32(qq[j])));
        }
#pragma unroll
        for (int k = 0; k < 10; k++) atomicAdd(&g_deg[idx[k]], 1);
    }
    if (v1) {
        const int bR = o1 ? 0 : 5, bP = 5 - bR;
#pragma unroll
        for (int j = 0; j < 5; j++) {
            atomicAdd(&g_agg[idx[10 + bR + j]],  sigmoidf(hi32(rr[j])));
            atomicAdd(&g_agg[idx[10 + bP + j]], -sigmoidf(hi32(qq[j])));
        }
#pragma unroll
        for (int k = 0; k < 10; k++) atomicAdd(&g_deg[idx[10 + k]], 1);
    }
}

__device__ __forceinline__ float warp_sum(float v) {
#pragma unroll
    for (int s = 16; s; s >>= 1) v += __shfl_xor_sync(0xffffffffu, v, s);
    return v;
}
__device__ __forceinline__ int warp_max(int v) {
#pragma unroll
    for (int s = 16; s; s >>= 1) v = max(v, __shfl_xor_sync(0xffffffffu, v, s));
    return v;
}

__global__ void reduce1_kernel(const float* __restrict__ score, int N) {
    int i = blockIdx.x * blockDim.x + threadIdx.x;
    int d = 0; float sa = 0.0f, ss = 0.0f;
    if (i < N) { d = g_deg[i]; sa = g_agg[i]; ss = score[i]; }
    sa = warp_sum(sa); ss = warp_sum(ss); d = warp_max(d);
    if ((threadIdx.x & 31) == 0) {
        atomicMax(&g_degmax, d);
        atomicAdd(&g_sum_agg, sa);
        atomicAdd(&g_sum_score, ss);
    }
}

__global__ void reduce2_kernel(const float* __restrict__ score, int N) {
    const float c    = 2.0f / (float)g_degmax;          // NORM_FACTOR / deg.max()
    const float mean = (g_sum_score + c * g_sum_agg) / (float)N;
    int i = blockIdx.x * blockDim.x + threadIdx.x;
    float u = 0.0f;
    if (i < N) { u = score[i] + c * g_agg[i] - mean; g_tmp[i] = u; }
    float sq = warp_sum(u * u);
    if ((threadIdx.x & 31) == 0) atomicAdd(&g_sumsq, sq);
}

__global__ void finalize_kernel(float* __restrict__ out, int N) {
    int i = blockIdx.x * blockDim.x + threadIdx.x;
    if (i < N) out[i] = g_tmp[i] * rsqrtf(g_sumsq);
}

// ---------------- launch ----------------
extern "C" void kernel_launch(void* const* d_in, const int* in_sizes, int n_in,
                              void* d_out, int out_size) {
    const float* score    = (const float*)d_in[0];
    const int*   edge_idx = (const int*)  d_in[1];
    const float* outcome  = (const float*)d_in[2];
    const float* Rsw = (const float*)d_in[3],  *Rsb = (const float*)d_in[4];
    const float* Rhw = (const float*)d_in[5],  *Rhb = (const float*)d_in[6];
    const float* Rew = (const float*)d_in[7],  *Reb = (const float*)d_in[8];
    const float* Psw = (const float*)d_in[9],  *Psb = (const float*)d_in[10];
    const float* Phw = (const float*)d_in[11], *Phb = (const float*)d_in[12];
    const float* Pew = (const float*)d_in[13], *Peb = (const float*)d_in[14];

    const int N = in_sizes[0];   // score is (N, 1)
    const int E = in_sizes[2];   // outcome is (E,)

    cudaFuncSetAttribute(edge_kernel,
                         cudaFuncAttributeMaxDynamicSharedMemorySize, SMEM_BYTES);

    const int tb = 256, nb = (N + tb - 1) / tb;
    zero_kernel<<<nb, tb>>>(N);

    const int P = (E + 1) / 2;
    edge_kernel<<<(P + 127) / 128, 128, SMEM_BYTES>>>(
        score, edge_idx, outcome,
        Rsw, Rsb, Rhw, Rhb, Rew, Reb,
        Psw, Psb, Phw, Phb, Pew, Peb, E);

    reduce1_kernel<<<nb, tb>>>(score, N);
    reduce2_kernel<<<nb, tb>>>(score, N);
    finalize_kernel<<<nb, tb>>>((float*)d_out, N);
}

// round 3
// speedup vs baseline: 1.0583x; 1.0583x over previous
#include <cuda_runtime.h>
#include <cuda_bf16.h>

typedef unsigned long long u64;

#define NMAX 100000

// ---------------- device scratch (no allocations allowed) ----------------
__device__ float g_agg[NMAX];
__device__ int   g_deg[NMAX];
__device__ float g_tmp[NMAX];
__device__ int   g_degmax;
__device__ float g_sum_agg;
__device__ float g_sum_score;
__device__ float g_sumsq;

// ---------------- smem weight layout (units: u64 = {w[2jp][i], w[2jp+1][i]}) --
// Output rows padded 35 -> 36 (18 pairs), hidden row stride padded 35 -> 36
// pairs so every row base is 16B aligned (even u64 index).
#define OFF_SW 0        // 18 jp x 10 i, stride 10      (180)
#define OFF_SB 180      // 18 pairs                      (18)
#define OFF_HW 198      // 3 x (18 jp x 36), per-layer 648   (1944)
#define OFF_HB 2142     // 3 x 18                        (54)
#define OFF_EW 2196     // 3 jp x 36 stride              (108)
#define OFF_EB 2304     // 3                             (3)
#define NET_STRIDE 2308
#define SMEM_U64 (2 * NET_STRIDE)   // 4616 u64 = 36928 B (static smem)

// ---------------- packed f32x2 helpers ----------------
__device__ __forceinline__ u64 fma2(u64 a, u64 b, u64 c) {
    u64 d;
    asm("fma.rn.f32x2 %0, %1, %2, %3;" : "=l"(d) : "l"(a), "l"(b), "l"(c));
    return d;
}
__device__ __forceinline__ u64 dup(float v) {
    unsigned b = __float_as_uint(v);
    return ((u64)b << 32) | (u64)b;
}
__device__ __forceinline__ float lo32(u64 a) { return __uint_as_float((unsigned)a); }
__device__ __forceinline__ float hi32(u64 a) { return __uint_as_float((unsigned)(a >> 32)); }
__device__ __forceinline__ float sigmoidf(float v) {
    return 1.0f / (1.0f + __expf(-v));
}

// One dense layer, output-pair packed.
// {y[2jp], y[2jp+1]} = (relu) (b_pair[jp] + sum_i w_pair[jp][i] * {x_i, x_i})
template<int NPAIR, int NIN, int STRIDE, bool RELU>
__device__ __forceinline__ void dense(const u64* __restrict__ w,
                                      const u64* __restrict__ b,
                                      const u64* __restrict__ xd,
                                      float* __restrict__ y) {
#pragma unroll
    for (int jp = 0; jp < NPAIR; jp++) {
        u64 acc = b[jp];
        const u64* wr = w + jp * STRIDE;
#pragma unroll
        for (int i = 0; i + 1 < NIN; i += 2) {
            ulonglong2 w2 = *reinterpret_cast<const ulonglong2*>(wr + i);
            acc = fma2(w2.x, xd[i], acc);
            acc = fma2(w2.y, xd[i + 1], acc);
        }
        if (NIN & 1) acc = fma2(wr[NIN - 1], xd[NIN - 1], acc);
        float l = lo32(acc), h = hi32(acc);
        if (RELU) { l = fmaxf(l, 0.0f); h = fmaxf(h, 0.0f); }
        y[2 * jp] = l; y[2 * jp + 1] = h;
    }
}

// ---------------- kernels ----------------
__global__ void zero_kernel(int N) {
    int i = blockIdx.x * blockDim.x + threadIdx.x;
    if (i < N) { g_agg[i] = 0.0f; g_deg[i] = 0; }
    if (i == 0) { g_degmax = 0; g_sum_agg = 0.0f; g_sum_score = 0.0f; g_sumsq = 0.0f; }
}

__global__ void __launch_bounds__(128, 3) edge_kernel(
    const float* __restrict__ score,
    const int*   __restrict__ edge_idx,
    const float* __restrict__ outcome,
    const float* __restrict__ Rsw, const float* __restrict__ Rsb,
    const float* __restrict__ Rhw, const float* __restrict__ Rhb,
    const float* __restrict__ Rew, const float* __restrict__ Reb,
    const float* __restrict__ Psw, const float* __restrict__ Psb,
    const float* __restrict__ Phw, const float* __restrict__ Phb,
    const float* __restrict__ Pew, const float* __restrict__ Peb,
    int E)
{
    __shared__ __align__(16) u64 wsm[SMEM_U64];
    float* wf = reinterpret_cast<float*>(wsm);
    const int t = threadIdx.x, nt = blockDim.x;

    // zero-fill (padded slots must be 0)
    for (int k = t; k < 2 * SMEM_U64; k += nt) wf[k] = 0.0f;
    __syncthreads();

    // scatter weights into pair-interleaved layout.
    // NOTE: pairing must restart at each matrix boundary, so the three stacked
    // hidden matrices are scattered with separate calls.
    auto putm = [&](const float* __restrict__ s, int offU, int rows, int cols, int stride) {
        int n = rows * cols;
        for (int k = t; k < n; k += nt) {
            int j = k / cols, i = k - j * cols;
            wf[(offU + (j >> 1) * stride + i) * 2 + (j & 1)] = s[k];
        }
    };
    auto putv = [&](const float* __restrict__ s, int offU, int n) {
        for (int j = t; j < n; j += nt)
            wf[(offU + (j >> 1)) * 2 + (j & 1)] = s[j];
    };
    // R net
    putm(Rsw, OFF_SW, 35, 10, 10);
    putv(Rsb, OFF_SB, 35);
#pragma unroll
    for (int m = 0; m < 3; m++) {
        putm(Rhw + m * 35 * 35, OFF_HW + m * 648, 35, 35, 36);
        putv(Rhb + m * 35,      OFF_HB + m * 18, 35);
    }
    putm(Rew, OFF_EW, 5, 35, 36);     // only first 5 output rows needed
    putv(Reb, OFF_EB, 5);
    // P net
    putm(Psw, NET_STRIDE + OFF_SW, 35, 10, 10);
    putv(Psb, NET_STRIDE + OFF_SB, 35);
#pragma unroll
    for (int m = 0; m < 3; m++) {
        putm(Phw + m * 35 * 35, NET_STRIDE + OFF_HW + m * 648, 35, 35, 36);
        putv(Phb + m * 35,      NET_STRIDE + OFF_HB + m * 18, 35);
    }
    putm(Pew, NET_STRIDE + OFF_EW, 5, 35, 36);
    putv(Peb, NET_STRIDE + OFF_EB, 5);
    __syncthreads();

    const int e = blockIdx.x * blockDim.x + t;
    if (e >= E) return;

    // gather indices (40B row, 8B aligned) and scores
    int idx[10];
    {
        const int2* ei2 = reinterpret_cast<const int2*>(edge_idx + (size_t)e * 10);
#pragma unroll
        for (int k = 0; k < 5; k++) {
            int2 q = ei2[k];
            idx[2 * k] = q.x; idx[2 * k + 1] = q.y;
        }
    }
    float xsc[10];
#pragma unroll
    for (int i = 0; i < 10; i++) xsc[i] = score[idx[i]];

    const bool o = outcome[e] > 0.0f;

#pragma unroll 1
    for (int net = 0; net < 2; net++) {   // 0 = R (+sigmoid), 1 = P (-sigmoid)
        const u64* Wb = wsm + net * NET_STRIDE;
        const bool fwd = (net == 0) ? o : !o;

        u64 xd[36];
        float y[36];
#pragma unroll
        for (int i = 0; i < 10; i++) xd[i] = dup(fwd ? xsc[i] : xsc[9 - i]);

        dense<18, 10, 10, true >(Wb + OFF_SW,        Wb + OFF_SB,      xd, y);
#pragma unroll
        for (int i = 0; i < 36; i++) xd[i] = dup(y[i]);
        dense<18, 35, 36, true >(Wb + OFF_HW,        Wb + OFF_HB,      xd, y);
#pragma unroll
        for (int i = 0; i < 36; i++) xd[i] = dup(y[i]);
        dense<18, 35, 36, true >(Wb + OFF_HW +  648, Wb + OFF_HB + 18, xd, y);
#pragma unroll
        for (int i = 0; i < 36; i++) xd[i] = dup(y[i]);
        dense<18, 35, 36, true >(Wb + OFF_HW + 1296, Wb + OFF_HB + 36, xd, y);
#pragma unroll
        for (int i = 0; i < 36; i++) xd[i] = dup(y[i]);
        dense< 3, 35, 36, false>(Wb + OFF_EW,        Wb + OFF_EB,      xd, y);

        // scatter this net's 5 contributions
        const int  base = (net == 0) ? (o ? 0 : 5) : (o ? 5 : 0);
        const float sgn = (net == 0) ? 1.0f : -1.0f;
#pragma unroll
        for (int j = 0; j < 5; j++)
            atomicAdd(&g_agg[idx[base + j]], sgn * sigmoidf(y[j]));
    }

#pragma unroll
    for (int k = 0; k < 10; k++) atomicAdd(&g_deg[idx[k]], 1);
}

__device__ __forceinline__ float warp_sum(float v) {
#pragma unroll
    for (int s = 16; s; s >>= 1) v += __shfl_xor_sync(0xffffffffu, v, s);
    return v;
}
__device__ __forceinline__ int warp_max(int v) {
#pragma unroll
    for (int s = 16; s; s >>= 1) v = max(v, __shfl_xor_sync(0xffffffffu, v, s));
    return v;
}

__global__ void reduce1_kernel(const float* __restrict__ score, int N) {
    int i = blockIdx.x * blockDim.x + threadIdx.x;
    int d = 0; float sa = 0.0f, ss = 0.0f;
    if (i < N) { d = g_deg[i]; sa = g_agg[i]; ss = score[i]; }
    sa = warp_sum(sa); ss = warp_sum(ss); d = warp_max(d);
    if ((threadIdx.x & 31) == 0) {
        atomicMax(&g_degmax, d);
        atomicAdd(&g_sum_agg, sa);
        atomicAdd(&g_sum_score, ss);
    }
}

__global__ void reduce2_kernel(const float* __restrict__ score, int N) {
    const float c    = 2.0f / (float)g_degmax;          // NORM_FACTOR / deg.max()
    const float mean = (g_sum_score + c * g_sum_agg) / (float)N;
    int i = blockIdx.x * blockDim.x + threadIdx.x;
    float u = 0.0f;
    if (i < N) { u = score[i] + c * g_agg[i] - mean; g_tmp[i] = u; }
    float sq = warp_sum(u * u);
    if ((threadIdx.x & 31) == 0) atomicAdd(&g_sumsq, sq);
}

__global__ void finalize_kernel(float* __restrict__ out, int N) {
    int i = blockIdx.x * blockDim.x + threadIdx.x;
    if (i < N) out[i] = g_tmp[i] * rsqrtf(g_sumsq);
}

// ---------------- launch ----------------
extern "C" void kernel_launch(void* const* d_in, const int* in_sizes, int n_in,
                              void* d_out, int out_size) {
    const float* score    = (const float*)d_in[0];
    const int*   edge_idx = (const int*)  d_in[1];
    const float* outcome  = (const float*)d_in[2];
    const float* Rsw = (const float*)d_in[3],  *Rsb = (const float*)d_in[4];
    const float* Rhw = (const float*)d_in[5],  *Rhb = (const float*)d_in[6];
    const float* Rew = (const float*)d_in[7],  *Reb = (const float*)d_in[8];
    const float* Psw = (const float*)d_in[9],  *Psb = (const float*)d_in[10];
    const float* Phw = (const float*)d_in[11], *Phb = (const float*)d_in[12];
    const float* Pew = (const float*)d_in[13], *Peb = (const float*)d_in[14];

    const int N = in_sizes[0];   // score is (N, 1)
    const int E = in_sizes[2];   // outcome is (E,)

    const int tb = 256, nb = (N + tb - 1) / tb;
    zero_kernel<<<nb, tb>>>(N);

    edge_kernel<<<(E + 127) / 128, 128>>>(
        score, edge_idx, outcome,
        Rsw, Rsb, Rhw, Rhb, Rew, Reb,
        Psw, Psb, Phw, Phb, Pew, Peb, E);

    reduce1_kernel<<<nb, tb>>>(score, N);
    reduce2_kernel<<<nb, tb>>>(score, N);
    finalize_kernel<<<nb, tb>>>((float*)d_out, N);
}